// round 4
// baseline (speedup 1.0000x reference)
#include <cuda_runtime.h>
#include <cstdint>

// ---------------- compile-time shape constants (this problem's shapes) --------
#define KK3   27     // neighbors per voxel
#define CIN   64     // input channels  (== K-chunk size; 1 chunk == 1 neighbor)
#define COUT  128    // output channels
#define TM    64     // rows per block
#define NTHR  256    // threads per block

// ---------------- cp.async helpers ----------------
__device__ __forceinline__ void cp16(uint32_t dst, const void* src, int srcsize) {
    asm volatile("cp.async.cg.shared.global [%0], [%1], 16, %2;\n"
                 :: "r"(dst), "l"(src), "r"(srcsize));
}
__device__ __forceinline__ void cp_commit() {
    asm volatile("cp.async.commit_group;\n" ::);
}
template <int N>
__device__ __forceinline__ void cp_wait() {
    asm volatile("cp.async.wait_group %0;\n" :: "n"(N));
}

// =============================================================================
// Fused gather + GEMM + LayerNorm + ReLU for exactly the B*K resampled rows.
// NOTE: voxel_idx is int32 (JAX x64-disabled downgrades jnp.int64 -> int32).
// =============================================================================
__global__ __launch_bounds__(NTHR)
void fused_block_kernel(const float* __restrict__ features,
                        const int* __restrict__ voxel_idx,
                        const int* __restrict__ num_list,
                        const float* __restrict__ W,
                        const float* __restrict__ gamma,
                        const float* __restrict__ beta,
                        float* __restrict__ outF,
                        int N, int M, int B, int K, int BK)
{
    extern __shared__ float smem[];
    float* As   = smem;                       // 2*TM*CIN
    float* Bs   = As + 2 * TM * CIN;          // 2*CIN*COUT
    int*   sIdx = (int*)(Bs + 2 * CIN * COUT);
    int*   sSrc = sIdx + TM * KK3;
    int*   sVal = sSrc + TM;

    const int tid = threadIdx.x;
    const int r0  = blockIdx.x * TM;

    // ---- per-row resample bookkeeping (offsets from cumsum of num_list) ----
    if (tid < TM) {
        int g = r0 + tid;
        int valid = 0;
        int srcRow = 0;
        if (g < BK) {
            int b = g / K;
            int j = g - b * K;
            int off = 0;
            for (int bb = 0; bb < b; bb++) off += num_list[bb];
            int nl  = num_list[b];
            int end = nl < K ? nl : K;
            valid = (j < end) ? 1 : 0;
            long long s = (long long)off + j;
            if (s < 0) s = 0;
            if (s > (long long)(M - 1)) s = M - 1;
            srcRow = (int)s;
        }
        sVal[tid] = valid;
        sSrc[tid] = srcRow;
    }
    __syncthreads();

    // ---- stage all neighbor indices for this tile. clip to [0, N-1];
    //      negative => -1 (padding) ----
    for (int e = tid; e < TM * KK3; e += NTHR) {
        int m = e / KK3, c = e - m * KK3;
        int v = voxel_idx[(long long)sSrc[m] * KK3 + c];
        int iv;
        if (v < 0)           iv = -1;
        else if (v > N - 1)  iv = N - 1;
        else                 iv = v;
        sIdx[e] = iv;
    }
    __syncthreads();

    const uint32_t asAddr = (uint32_t)__cvta_generic_to_shared(As);
    const uint32_t bsAddr = (uint32_t)__cvta_generic_to_shared(Bs);

    // ---- cp.async staging of one K-chunk (== one neighbor) ----
    auto prefetch = [&](int c, int buf) {
        // A: gathered features, 64 rows x 64 ch. 16 float4-lanes per row.
        int c4   = tid & 15;
        int mrow = tid >> 4;
        #pragma unroll
        for (int r = 0; r < 4; r++) {
            int m   = mrow + 16 * r;
            int idx = sIdx[m * KK3 + c];
            const float* src = features + (long long)(idx < 0 ? 0 : idx) * CIN + 4 * c4;
            uint32_t dst = asAddr + (uint32_t)(((buf * TM + m) * CIN + 4 * c4) * 4);
            cp16(dst, src, idx < 0 ? 0 : 16);
        }
        // B: W chunk, 64 rows x 128 cols. 32 float4-lanes per row.
        int c8   = tid & 31;
        int brow = tid >> 5;
        #pragma unroll
        for (int r = 0; r < 8; r++) {
            int row = brow + 8 * r;
            const float* src = W + (long long)(c * CIN + row) * COUT + 4 * c8;
            uint32_t dst = bsAddr + (uint32_t)(((buf * CIN + row) * COUT + 4 * c8) * 4);
            cp16(dst, src, 16);
        }
    };

    // ---- main pipelined GEMM: 4x8 micro-tile per thread ----
    float acc[4][8];
    #pragma unroll
    for (int i = 0; i < 4; i++)
        #pragma unroll
        for (int j = 0; j < 8; j++) acc[i][j] = 0.0f;

    const int tx = tid & 15;   // column group: cols {4tx..4tx+3} and {64+4tx..}
    const int ty = tid >> 4;   // row group:   rows 4ty..4ty+3

    prefetch(0, 0);
    cp_commit();

    for (int c = 0; c < KK3; c++) {
        int buf = c & 1;
        if (c + 1 < KK3) { prefetch(c + 1, buf ^ 1); cp_commit(); cp_wait<1>(); }
        else             { cp_wait<0>(); }
        __syncthreads();

        const float* A  = As + buf * TM * CIN;
        const float* Bt = Bs + buf * CIN * COUT;

        #pragma unroll
        for (int kk = 0; kk < CIN; kk++) {
            float a0 = A[(4 * ty + 0) * CIN + kk];
            float a1 = A[(4 * ty + 1) * CIN + kk];
            float a2 = A[(4 * ty + 2) * CIN + kk];
            float a3 = A[(4 * ty + 3) * CIN + kk];
            float4 b0 = *(const float4*)(Bt + kk * COUT + 4 * tx);
            float4 b1 = *(const float4*)(Bt + kk * COUT + 64 + 4 * tx);
            acc[0][0] += a0 * b0.x; acc[0][1] += a0 * b0.y; acc[0][2] += a0 * b0.z; acc[0][3] += a0 * b0.w;
            acc[0][4] += a0 * b1.x; acc[0][5] += a0 * b1.y; acc[0][6] += a0 * b1.z; acc[0][7] += a0 * b1.w;
            acc[1][0] += a1 * b0.x; acc[1][1] += a1 * b0.y; acc[1][2] += a1 * b0.z; acc[1][3] += a1 * b0.w;
            acc[1][4] += a1 * b1.x; acc[1][5] += a1 * b1.y; acc[1][6] += a1 * b1.z; acc[1][7] += a1 * b1.w;
            acc[2][0] += a2 * b0.x; acc[2][1] += a2 * b0.y; acc[2][2] += a2 * b0.z; acc[2][3] += a2 * b0.w;
            acc[2][4] += a2 * b1.x; acc[2][5] += a2 * b1.y; acc[2][6] += a2 * b1.z; acc[2][7] += a2 * b1.w;
            acc[3][0] += a3 * b0.x; acc[3][1] += a3 * b0.y; acc[3][2] += a3 * b0.z; acc[3][3] += a3 * b0.w;
            acc[3][4] += a3 * b1.x; acc[3][5] += a3 * b1.y; acc[3][6] += a3 * b1.z; acc[3][7] += a3 * b1.w;
        }
        __syncthreads();
    }

    // ---- epilogue: LayerNorm (16-lane butterfly spans one row) + ReLU ----
    float4 gm0 = *(const float4*)(gamma + 4 * tx);
    float4 gm1 = *(const float4*)(gamma + 64 + 4 * tx);
    float4 bt0 = *(const float4*)(beta + 4 * tx);
    float4 bt1 = *(const float4*)(beta + 64 + 4 * tx);
    const float invC = 1.0f / (float)COUT;

    #pragma unroll
    for (int i = 0; i < 4; i++) {
        int m = 4 * ty + i;
        float s = 0.0f, sq = 0.0f;
        #pragma unroll
        for (int j = 0; j < 8; j++) { s += acc[i][j]; sq += acc[i][j] * acc[i][j]; }
        #pragma unroll
        for (int o = 1; o < 16; o <<= 1) {
            s  += __shfl_xor_sync(0xffffffffu, s,  o);
            sq += __shfl_xor_sync(0xffffffffu, sq, o);
        }
        float mu  = s * invC;
        float var = sq * invC - mu * mu;
        float rs  = rsqrtf(var + 1e-3f);

        int g = r0 + m;
        if (g < BK) {
            float4 o0, o1;
            if (sVal[m]) {
                o0.x = fmaxf((acc[i][0] - mu) * rs * gm0.x + bt0.x, 0.0f);
                o0.y = fmaxf((acc[i][1] - mu) * rs * gm0.y + bt0.y, 0.0f);
                o0.z = fmaxf((acc[i][2] - mu) * rs * gm0.z + bt0.z, 0.0f);
                o0.w = fmaxf((acc[i][3] - mu) * rs * gm0.w + bt0.w, 0.0f);
                o1.x = fmaxf((acc[i][4] - mu) * rs * gm1.x + bt1.x, 0.0f);
                o1.y = fmaxf((acc[i][5] - mu) * rs * gm1.y + bt1.y, 0.0f);
                o1.z = fmaxf((acc[i][6] - mu) * rs * gm1.z + bt1.z, 0.0f);
                o1.w = fmaxf((acc[i][7] - mu) * rs * gm1.w + bt1.w, 0.0f);
            } else {
                o0 = make_float4(0.f, 0.f, 0.f, 0.f);
                o1 = make_float4(0.f, 0.f, 0.f, 0.f);
            }
            *(float4*)(outF + (long long)g * COUT + 4 * tx)      = o0;
            *(float4*)(outF + (long long)g * COUT + 64 + 4 * tx) = o1;
        }
    }
}

// =============================================================================
// point_coords: col0 batch quirk written for ALL k; xyz masked by validity.
// =============================================================================
__global__ void coord_kernel(const float* __restrict__ center,
                             const int* __restrict__ num_list,
                             float* __restrict__ outC,
                             int M, int B, int K, int BK)
{
    int g = blockIdx.x * blockDim.x + threadIdx.x;
    if (g >= BK) return;
    int b = g / K, j = g - b * K;
    int off = 0;
    for (int bb = 0; bb < b; bb++) off += num_list[bb];
    int nl  = num_list[b];
    int end = nl < K ? nl : K;
    bool valid = (j < end);
    long long s = (long long)off + j;
    if (s < 0) s = 0;
    if (s > (long long)(M - 1)) s = M - 1;
    float c0 = (b < B - 1) ? (float)(b + 1) : 0.0f;
    float x = 0.f, y = 0.f, z = 0.f;
    if (valid) { x = center[s * 3 + 0]; y = center[s * 3 + 1]; z = center[s * 3 + 2]; }
    float4 o = make_float4(c0, x, y, z);
    *(float4*)(outC + (long long)g * 4) = o;
}

// =============================================================================
extern "C" void kernel_launch(void* const* d_in, const int* in_sizes, int n_in,
                              void* d_out, int out_size)
{
    const float* features = (const float*)d_in[0];
    const float* center   = (const float*)d_in[1];
    const int*   voxel    = (const int*)d_in[2];     // int32 (JAX x64 disabled)
    const int*   num_list = (const int*)d_in[3];
    const float* W        = (const float*)d_in[4];
    const float* gamma    = (const float*)d_in[5];
    const float* beta     = (const float*)d_in[6];

    int B     = in_sizes[3];
    int Cout  = in_sizes[5];                       // gamma length
    int M     = in_sizes[1] / 3;                   // center_coors rows
    int K3r   = in_sizes[2] / M;                   // neighbors
    int Cin   = in_sizes[4] / (K3r * Cout);        // W rows / K3
    int N     = in_sizes[0] / Cin;                 // feature rows
    int K     = out_size / (B * (Cout + 4));       // num_keypoints (derived)
    int BK    = B * K;

    float* out = (float*)d_out;

    size_t smem = (size_t)(2 * TM * CIN + 2 * CIN * COUT) * 4
                + (size_t)TM * KK3 * 4 + (size_t)TM * 2 * 4;

    cudaFuncSetAttribute(fused_block_kernel,
                         cudaFuncAttributeMaxDynamicSharedMemorySize, (int)smem);

    int grid = (BK + TM - 1) / TM;
    fused_block_kernel<<<grid, NTHR, smem>>>(features, voxel, num_list, W,
                                             gamma, beta, out,
                                             N, M, B, K, BK);

    coord_kernel<<<(BK + 255) / 256, 256>>>(center, num_list,
                                            out + (long long)BK * Cout,
                                            M, B, K, BK);
}

// round 6
// speedup vs baseline: 1.9910x; 1.9910x over previous
#include <cuda_runtime.h>
#include <cuda_bf16.h>
#include <cstdint>

// ---------------- problem shape constants ----------------
#define CHUNKS 27      // K3 neighbors = 27 K-chunks of 64
#define CIN    64
#define COUT   128
#define TM     64      // rows per CTA
#define NTHR   256

// ---------------- smem layout (bytes) ----------------
// A: 2 buffers x [hi 64x144 | lo 64x144]  = 2 x 18432
#define OFF_A    0
// B: 3 slots  x [hi 128x144 | lo 128x144] = 3 x 36864
#define OFF_B    36864
#define OFF_IDX  147456     // 64*27 ints
#define OFF_SRC  154368     // 64 ints
#define OFF_VAL  154624     // 64 ints
#define OFF_RED  154880     // 64*4 float2
#define SMEM_TOTAL 156928

#define A_BUF_B   18432
#define A_HALF_B  9216
#define B_SLOT_B  36864
#define B_HALF_B  18432
#define ROWSTRIDE 144        // bytes per bf16 row (128 data + 16 pad)

// W images: per chunk [hi 128x144][lo 128x144], n-major (row n, k contiguous)
__device__ __align__(16) unsigned char g_Wimg[CHUNKS * B_SLOT_B];

// ---------------- asm helpers ----------------
__device__ __forceinline__ uint32_t smem_u32(const void* p) {
    return (uint32_t)__cvta_generic_to_shared(p);
}
__device__ __forceinline__ void cp16(uint32_t dst, const void* src) {
    asm volatile("cp.async.cg.shared.global [%0], [%1], 16;\n" :: "r"(dst), "l"(src));
}
__device__ __forceinline__ void cp_commit() { asm volatile("cp.async.commit_group;\n" ::); }
template <int N> __device__ __forceinline__ void cp_wait() {
    asm volatile("cp.async.wait_group %0;\n" :: "n"(N));
}
__device__ __forceinline__ void sts128(uint32_t addr, const uint32_t* r) {
    asm volatile("st.shared.v4.b32 [%0], {%1,%2,%3,%4};"
                 :: "r"(addr), "r"(r[0]), "r"(r[1]), "r"(r[2]), "r"(r[3]) : "memory");
}
__device__ __forceinline__ void ldsm4(uint32_t* r, uint32_t addr) {
    asm volatile("ldmatrix.sync.aligned.m8n8.x4.shared.b16 {%0,%1,%2,%3}, [%4];"
                 : "=r"(r[0]), "=r"(r[1]), "=r"(r[2]), "=r"(r[3]) : "r"(addr));
}
__device__ __forceinline__ void mma16816(float* d, const uint32_t* a, const uint32_t* b) {
    asm volatile(
        "mma.sync.aligned.m16n8k16.row.col.f32.bf16.bf16.f32 "
        "{%0,%1,%2,%3}, {%4,%5,%6,%7}, {%8,%9}, {%0,%1,%2,%3};"
        : "+f"(d[0]), "+f"(d[1]), "+f"(d[2]), "+f"(d[3])
        : "r"(a[0]), "r"(a[1]), "r"(a[2]), "r"(a[3]), "r"(b[0]), "r"(b[1]));
}

// =============================================================================
// Prep: W [CHUNKS*CIN, COUT] fp32 -> per-chunk n-major bf16 hi/lo images.
// hi = fp32 truncated to bf16 (top 16 bits); lo = rn(v - hi).
// Image row n holds k=0..63 contiguously (64 bf16 = 128B + 16B pad).
// =============================================================================
__global__ void prep_w_kernel(const float* __restrict__ W) {
    int e = blockIdx.x * blockDim.x + threadIdx.x;   // e = c*COUT + n
    if (e >= CHUNKS * COUT) return;
    int c = e >> 7, n = e & 127;
    uint32_t hi[32], lo[32];
    #pragma unroll
    for (int k2 = 0; k2 < 32; k2++) {
        float v0 = W[(size_t)(c * CIN + 2 * k2 + 0) * COUT + n];
        float v1 = W[(size_t)(c * CIN + 2 * k2 + 1) * COUT + n];
        uint32_t u0 = __float_as_uint(v0), u1 = __float_as_uint(v1);
        hi[k2] = __byte_perm(u0, u1, 0x7632);        // {lo16: u0>>16, hi16: u1>>16}
        float h0 = __uint_as_float(u0 & 0xFFFF0000u);
        float h1 = __uint_as_float(u1 & 0xFFFF0000u);
        float l0 = v0 - h0, l1 = v1 - h1;
        asm("cvt.rn.bf16x2.f32 %0, %1, %2;" : "=r"(lo[k2]) : "f"(l1), "f"(l0));
    }
    unsigned char* dst = g_Wimg + (size_t)c * B_SLOT_B + (size_t)n * ROWSTRIDE;
    #pragma unroll
    for (int i = 0; i < 8; i++) ((uint4*)dst)[i] = ((const uint4*)hi)[i];
    dst += B_HALF_B;
    #pragma unroll
    for (int i = 0; i < 8; i++) ((uint4*)dst)[i] = ((const uint4*)lo)[i];
}

// =============================================================================
// Fused: gather + bf16x3 mma.sync GEMM + LayerNorm + ReLU + coords.
// Grid: BK/TM blocks. Warps: 2 (M) x 4 (N); warp tile 32x32.
// =============================================================================
__global__ __launch_bounds__(NTHR)
void fused_mma_kernel(const float* __restrict__ features,
                      const float* __restrict__ center,
                      const int* __restrict__ voxel_idx,
                      const int* __restrict__ num_list,
                      const float* __restrict__ gamma,
                      const float* __restrict__ beta,
                      float* __restrict__ outF,
                      float* __restrict__ outC,
                      int N, int M, int B, int K, int BK)
{
    extern __shared__ char smem[];
    const uint32_t sb = smem_u32(smem);
    int*    sIdx = (int*)(smem + OFF_IDX);
    int*    sSrc = (int*)(smem + OFF_SRC);
    int*    sVal = (int*)(smem + OFF_VAL);
    float2* sRed = (float2*)(smem + OFF_RED);

    const int tid = threadIdx.x;
    const int r0  = blockIdx.x * TM;

    // ---- bookkeeping + coords (tid < 64) ----
    if (tid < TM) {
        int g = r0 + tid;
        int valid = 0, srcRow = 0;
        int b = 0;
        if (g < BK) {
            b = g / K;
            int j = g - b * K;
            int off = 0;
            for (int bb = 0; bb < b; bb++) off += num_list[bb];
            int nl = num_list[b];
            int end = nl < K ? nl : K;
            valid = (j < end) ? 1 : 0;
            long long s = (long long)off + j;
            if (s < 0) s = 0;
            if (s > (long long)(M - 1)) s = M - 1;
            srcRow = (int)s;
        }
        sVal[tid] = valid;
        sSrc[tid] = srcRow;
        if (g < BK) {
            float c0 = (b < B - 1) ? (float)(b + 1) : 0.0f;
            float x = 0.f, y = 0.f, z = 0.f;
            if (valid) {
                x = center[(size_t)srcRow * 3 + 0];
                y = center[(size_t)srcRow * 3 + 1];
                z = center[(size_t)srcRow * 3 + 2];
            }
            *(float4*)(outC + (size_t)g * 4) = make_float4(c0, x, y, z);
        }
    }
    __syncthreads();

    // ---- stage neighbor indices ----
    for (int e = tid; e < TM * CHUNKS; e += NTHR) {
        int m = e / CHUNKS, c = e - m * CHUNKS;
        int v = voxel_idx[(size_t)sSrc[m] * CHUNKS + c];
        sIdx[e] = (v < 0) ? -1 : (v > N - 1 ? N - 1 : v);
    }
    __syncthreads();

    // ---- prologue: cp.async B0 (slot 0), LDG A0 ----
    for (int g = tid; g < B_SLOT_B / 16; g += NTHR)
        cp16(sb + OFF_B + g * 16, g_Wimg + (size_t)g * 16);
    cp_commit();

    const int m = tid >> 2, q = tid & 3;         // producer mapping: row m, ch quarter q
    float4 fa[4];
    {
        int idx = sIdx[m * CHUNKS + 0];
        if (idx >= 0) {
            const float4* p = (const float4*)features + (size_t)idx * 16 + q * 4;
            #pragma unroll
            for (int i = 0; i < 4; i++) fa[i] = p[i];
        } else {
            #pragma unroll
            for (int i = 0; i < 4; i++) fa[i] = make_float4(0.f, 0.f, 0.f, 0.f);
        }
    }

    // consumer mapping
    const int l  = tid & 31;
    const int wid = tid >> 5;
    const int wm = wid >> 2;                      // 0..1 (M)
    const int wn = wid & 3;                       // 0..3 (N)
    // ldmatrix lane address components
    const uint32_t aOff = (uint32_t)((wm * 32 + (l & 15)) * ROWSTRIDE + ((l >> 4) << 4));
    const uint32_t bOff = (uint32_t)((wn * 32 + ((l >> 4) << 3) + (l & 7)) * ROWSTRIDE
                                     + (((l >> 3) & 1) << 4));

    float acc[2][4][4];
    #pragma unroll
    for (int f = 0; f < 2; f++)
        #pragma unroll
        for (int g = 0; g < 4; g++)
            #pragma unroll
            for (int i = 0; i < 4; i++) acc[f][g][i] = 0.0f;

    // ---- mainloop ----
    for (int c = 0; c < CHUNKS; c++) {
        const int slot = c % 3, abuf = c & 1;

        // prefetch B[c+1]
        if (c + 1 < CHUNKS) {
            const unsigned char* src = g_Wimg + (size_t)(c + 1) * B_SLOT_B;
            uint32_t dst = sb + OFF_B + ((c + 1) % 3) * B_SLOT_B;
            for (int g = tid; g < B_SLOT_B / 16; g += NTHR)
                cp16(dst + g * 16, src + (size_t)g * 16);
            cp_commit();
        }

        // convert fa -> bf16 hi/lo, STS into A[abuf]
        {
            uint32_t hi[8], lo[8];
            const float* ff = (const float*)fa;
            #pragma unroll
            for (int i = 0; i < 8; i++) {
                float f0 = ff[2 * i], f1 = ff[2 * i + 1];
                uint32_t u0 = __float_as_uint(f0), u1 = __float_as_uint(f1);
                hi[i] = __byte_perm(u0, u1, 0x7632);
                float h0 = __uint_as_float(u0 & 0xFFFF0000u);
                float h1 = __uint_as_float(u1 & 0xFFFF0000u);
                float l0 = f0 - h0, l1 = f1 - h1;
                asm("cvt.rn.bf16x2.f32 %0, %1, %2;" : "=r"(lo[i]) : "f"(l1), "f"(l0));
            }
            uint32_t aB = sb + OFF_A + abuf * A_BUF_B + m * ROWSTRIDE + q * 32;
            sts128(aB,      hi);
            sts128(aB + 16, hi + 4);
            sts128(aB + A_HALF_B,      lo);
            sts128(aB + A_HALF_B + 16, lo + 4);
        }

        // LDG next chunk's A (hidden under compute)
        if (c + 1 < CHUNKS) {
            int idx = sIdx[m * CHUNKS + c + 1];
            if (idx >= 0) {
                const float4* p = (const float4*)features + (size_t)idx * 16 + q * 4;
                #pragma unroll
                for (int i = 0; i < 4; i++) fa[i] = p[i];
            } else {
                #pragma unroll
                for (int i = 0; i < 4; i++) fa[i] = make_float4(0.f, 0.f, 0.f, 0.f);
            }
        }

        if (c + 1 < CHUNKS) cp_wait<1>(); else cp_wait<0>();
        __syncthreads();

        const uint32_t aHi = sb + OFF_A + abuf * A_BUF_B + aOff;
        const uint32_t aLo = aHi + A_HALF_B;
        const uint32_t bHi = sb + OFF_B + slot * B_SLOT_B + bOff;
        const uint32_t bLo = bHi + B_HALF_B;

        #pragma unroll
        for (int ks = 0; ks < 4; ks++) {
            uint32_t ah[2][4], al[2][4], bh[2][4], bl[2][4];
            ldsm4(ah[0], aHi + ks * 32);
            ldsm4(ah[1], aHi + 16 * ROWSTRIDE + ks * 32);
            ldsm4(al[0], aLo + ks * 32);
            ldsm4(al[1], aLo + 16 * ROWSTRIDE + ks * 32);
            ldsm4(bh[0], bHi + ks * 32);
            ldsm4(bh[1], bHi + 16 * ROWSTRIDE + ks * 32);
            ldsm4(bl[0], bLo + ks * 32);
            ldsm4(bl[1], bLo + 16 * ROWSTRIDE + ks * 32);
            #pragma unroll
            for (int f = 0; f < 2; f++) {
                #pragma unroll
                for (int g = 0; g < 4; g++) {
                    const uint32_t* Bh = &bh[g >> 1][(g & 1) * 2];
                    const uint32_t* Bl = &bl[g >> 1][(g & 1) * 2];
                    mma16816(acc[f][g], ah[f], Bh);   // hi*hi
                    mma16816(acc[f][g], ah[f], Bl);   // hi*lo
                    mma16816(acc[f][g], al[f], Bh);   // lo*hi
                }
            }
        }
    }

    // ---- epilogue: LayerNorm + ReLU, register-resident ----
    #pragma unroll
    for (int f = 0; f < 2; f++) {
        #pragma unroll
        for (int rb = 0; rb < 2; rb++) {
            float s = 0.f, sq = 0.f;
            #pragma unroll
            for (int g = 0; g < 4; g++) {
                float v0 = acc[f][g][rb * 2], v1 = acc[f][g][rb * 2 + 1];
                s += v0 + v1;
                sq += v0 * v0 + v1 * v1;
            }
            s  += __shfl_xor_sync(0xffffffffu, s, 1);
            sq += __shfl_xor_sync(0xffffffffu, sq, 1);
            s  += __shfl_xor_sync(0xffffffffu, s, 2);
            sq += __shfl_xor_sync(0xffffffffu, sq, 2);
            if ((l & 3) == 0) {
                int R = wm * 32 + f * 16 + rb * 8 + (l >> 2);
                sRed[R * 4 + wn] = make_float2(s, sq);
            }
        }
    }
    __syncthreads();

    const float invC = 1.0f / (float)COUT;
    #pragma unroll
    for (int f = 0; f < 2; f++) {
        #pragma unroll
        for (int rb = 0; rb < 2; rb++) {
            int R = wm * 32 + f * 16 + rb * 8 + (l >> 2);
            float2 t0 = sRed[R * 4 + 0], t1 = sRed[R * 4 + 1];
            float2 t2 = sRed[R * 4 + 2], t3 = sRed[R * 4 + 3];
            float st  = t0.x + t1.x + t2.x + t3.x;
            float sqt = t0.y + t1.y + t2.y + t3.y;
            float mu  = st * invC;
            float var = sqt * invC - mu * mu;
            float rs  = rsqrtf(var + 1e-3f);
            int valid = sVal[R];
            int grow  = r0 + R;
            if (grow < BK) {
                float* op = outF + (size_t)grow * COUT;
                #pragma unroll
                for (int g = 0; g < 4; g++) {
                    int C = wn * 32 + g * 8 + (l & 3) * 2;
                    float2 gm = *(const float2*)(gamma + C);
                    float2 bt = *(const float2*)(beta + C);
                    float v0 = acc[f][g][rb * 2], v1 = acc[f][g][rb * 2 + 1];
                    float2 o;
                    o.x = valid ? fmaxf((v0 - mu) * rs * gm.x + bt.x, 0.f) : 0.f;
                    o.y = valid ? fmaxf((v1 - mu) * rs * gm.y + bt.y, 0.f) : 0.f;
                    *(float2*)(op + C) = o;
                }
            }
        }
    }
}

// =============================================================================
extern "C" void kernel_launch(void* const* d_in, const int* in_sizes, int n_in,
                              void* d_out, int out_size)
{
    const float* features = (const float*)d_in[0];
    const float* center   = (const float*)d_in[1];
    const int*   voxel    = (const int*)d_in[2];     // int32 (JAX x64 disabled)
    const int*   num_list = (const int*)d_in[3];
    const float* W        = (const float*)d_in[4];
    const float* gamma    = (const float*)d_in[5];
    const float* beta     = (const float*)d_in[6];

    int B    = in_sizes[3];
    int Cout = in_sizes[5];
    int M    = in_sizes[1] / 3;
    int K3r  = in_sizes[2] / M;
    int Cin  = in_sizes[4] / (K3r * Cout);
    int N    = in_sizes[0] / Cin;
    int K    = out_size / (B * (Cout + 4));
    int BK   = B * K;

    float* out  = (float*)d_out;
    float* outC = out + (size_t)BK * Cout;

    // W -> bf16 hi/lo n-major images
    int totalW = CHUNKS * COUT;
    prep_w_kernel<<<(totalW + 127) / 128, 128>>>(W);

    cudaFuncSetAttribute(fused_mma_kernel,
                         cudaFuncAttributeMaxDynamicSharedMemorySize, SMEM_TOTAL);

    int grid = (BK + TM - 1) / TM;
    fused_mma_kernel<<<grid, NTHR, SMEM_TOTAL>>>(
        features, center, voxel, num_list, gamma, beta, out, outC,
        N, M, B, K, BK);
}

// round 7
// speedup vs baseline: 2.1474x; 1.0786x over previous
#include <cuda_runtime.h>
#include <cuda_bf16.h>
#include <cstdint>

// ---------------- problem shape constants ----------------
#define CHUNKS 27      // K3 neighbors = 27 K-chunks of 64
#define CIN    64
#define COUT   128
#define TM     64      // rows per CTA
#define NTHR   256

// A smem: 2 buffers x [hi 64x144B | lo 64x144B]
#define A_ROW   144
#define A_HALF  (64 * A_ROW)        // 9216
#define A_BUF   (2 * A_HALF)       // 18432

// B fragment images: [27][4 ks][8 n16blk][32 lanes] x uint4 (16B), hi and lo
#define BFRAG_N (CHUNKS * 4 * 8 * 32)
__device__ __align__(16) uint4 g_BfragHi[BFRAG_N];
__device__ __align__(16) uint4 g_BfragLo[BFRAG_N];

// ---------------- asm helpers ----------------
__device__ __forceinline__ uint32_t smem_u32(const void* p) {
    return (uint32_t)__cvta_generic_to_shared(p);
}
__device__ __forceinline__ void sts128(uint32_t addr, const uint32_t* r) {
    asm volatile("st.shared.v4.b32 [%0], {%1,%2,%3,%4};"
                 :: "r"(addr), "r"(r[0]), "r"(r[1]), "r"(r[2]), "r"(r[3]) : "memory");
}
__device__ __forceinline__ void ldsm4(uint32_t* r, uint32_t addr) {
    asm volatile("ldmatrix.sync.aligned.m8n8.x4.shared.b16 {%0,%1,%2,%3}, [%4];"
                 : "=r"(r[0]), "=r"(r[1]), "=r"(r[2]), "=r"(r[3]) : "r"(addr));
}
__device__ __forceinline__ void mma16816(float* d, const uint32_t* a, const uint32_t* b) {
    asm volatile(
        "mma.sync.aligned.m16n8k16.row.col.f32.bf16.bf16.f32 "
        "{%0,%1,%2,%3}, {%4,%5,%6,%7}, {%8,%9}, {%0,%1,%2,%3};"
        : "+f"(d[0]), "+f"(d[1]), "+f"(d[2]), "+f"(d[3])
        : "r"(a[0]), "r"(a[1]), "r"(a[2]), "r"(a[3]), "r"(b[0]), "r"(b[1]));
}
__device__ __forceinline__ uint32_t pack_hi(float v0, float v1) {
    return __byte_perm(__float_as_uint(v0), __float_as_uint(v1), 0x7632);
}
__device__ __forceinline__ uint32_t pack_lo(float v0, float v1) {
    float h0 = __uint_as_float(__float_as_uint(v0) & 0xFFFF0000u);
    float h1 = __uint_as_float(__float_as_uint(v1) & 0xFFFF0000u);
    float l0 = v0 - h0, l1 = v1 - h1;
    uint32_t r;
    asm("cvt.rn.bf16x2.f32 %0, %1, %2;" : "=r"(r) : "f"(l1), "f"(l0));
    return r;
}

// =============================================================================
// Prep: W [CHUNKS*CIN, COUT] fp32 -> bf16 hi/lo images in EXACT mma B-fragment
// order. Entry e = ((c*4+ks)*8 + t)*32 + l holds the 4 regs lane l of an
// n16-block-t warp needs at k-step ks: [b0(n=16t+l/4), b1(same), b0(n+8), b1(n+8)]
// where b0 = {B[kb], B[kb+1]}, b1 = {B[kb+8], B[kb+9]}, kb = 16ks + 2(l%4).
// =============================================================================
__global__ void prep_b_kernel(const float* __restrict__ W) {
    int e = blockIdx.x * blockDim.x + threadIdx.x;
    if (e >= BFRAG_N) return;
    int l  = e & 31;
    int t  = (e >> 5) & 7;
    int ks = (e >> 8) & 3;
    int c  = e >> 10;
    int r = l & 3, ncol = l >> 2;
    int n0 = t * 16 + ncol, n1 = n0 + 8;
    int kb = ks * 16 + 2 * r;
    const float* Wc = W + (size_t)c * CIN * COUT;
    float v0 = Wc[(size_t)(kb + 0) * COUT + n0];
    float v1 = Wc[(size_t)(kb + 1) * COUT + n0];
    float v2 = Wc[(size_t)(kb + 8) * COUT + n0];
    float v3 = Wc[(size_t)(kb + 9) * COUT + n0];
    float v4 = Wc[(size_t)(kb + 0) * COUT + n1];
    float v5 = Wc[(size_t)(kb + 1) * COUT + n1];
    float v6 = Wc[(size_t)(kb + 8) * COUT + n1];
    float v7 = Wc[(size_t)(kb + 9) * COUT + n1];
    uint4 hi, lo;
    hi.x = pack_hi(v0, v1); hi.y = pack_hi(v2, v3);
    hi.z = pack_hi(v4, v5); hi.w = pack_hi(v6, v7);
    lo.x = pack_lo(v0, v1); lo.y = pack_lo(v2, v3);
    lo.z = pack_lo(v4, v5); lo.w = pack_lo(v6, v7);
    g_BfragHi[e] = hi;
    g_BfragLo[e] = lo;
}

// =============================================================================
// Fused: gather + bf16x3 mma.sync GEMM + LayerNorm + ReLU + coords.
// Grid: BK/TM. 8 warps, grid 1(M) x 8(N); warp tile 64x16. B via LDG fragments.
// =============================================================================
__global__ __launch_bounds__(NTHR)
void fused_mma_kernel(const float* __restrict__ features,
                      const float* __restrict__ center,
                      const int* __restrict__ voxel_idx,
                      const int* __restrict__ num_list,
                      const float* __restrict__ gamma,
                      const float* __restrict__ beta,
                      float* __restrict__ outF,
                      float* __restrict__ outC,
                      int N, int M, int B, int K, int BK)
{
    __shared__ __align__(16) unsigned char sA[A_BUF * 2];   // 36864
    __shared__ int    sIdx[TM * CHUNKS];
    __shared__ int    sSrc[TM];
    __shared__ int    sVal[TM];
    __shared__ float2 sRed[TM * 8];

    const uint32_t sAb = smem_u32(sA);
    const int tid = threadIdx.x;
    const int r0  = blockIdx.x * TM;

    // ---- bookkeeping + coords (tid < 64) ----
    if (tid < TM) {
        int g = r0 + tid;
        int valid = 0, srcRow = 0, b = 0;
        if (g < BK) {
            b = g / K;
            int j = g - b * K;
            int off = 0;
            for (int bb = 0; bb < b; bb++) off += num_list[bb];
            int nl = num_list[b];
            int end = nl < K ? nl : K;
            valid = (j < end) ? 1 : 0;
            long long s = (long long)off + j;
            if (s < 0) s = 0;
            if (s > (long long)(M - 1)) s = M - 1;
            srcRow = (int)s;
        }
        sVal[tid] = valid;
        sSrc[tid] = srcRow;
        if (g < BK) {
            float c0 = (b < B - 1) ? (float)(b + 1) : 0.0f;
            float x = 0.f, y = 0.f, z = 0.f;
            if (valid) {
                x = center[(size_t)srcRow * 3 + 0];
                y = center[(size_t)srcRow * 3 + 1];
                z = center[(size_t)srcRow * 3 + 2];
            }
            *(float4*)(outC + (size_t)g * 4) = make_float4(c0, x, y, z);
        }
    }
    __syncthreads();

    // ---- stage neighbor indices ----
    for (int e = tid; e < TM * CHUNKS; e += NTHR) {
        int m = e / CHUNKS, c = e - m * CHUNKS;
        int v = voxel_idx[(size_t)sSrc[m] * CHUNKS + c];
        sIdx[e] = (v < 0) ? -1 : (v > N - 1 ? N - 1 : v);
    }
    __syncthreads();

    // producer mapping
    const int m = tid >> 2, q = tid & 3;
    // consumer mapping: 1(M) x 8(N) warp grid, warp tile 64x16
    const int l  = tid & 31;
    const int wn = tid >> 5;      // 0..7
    const uint32_t aOffBase = (uint32_t)((l & 15) * A_ROW + ((l >> 4) << 4));

    float acc[4][2][4];
    #pragma unroll
    for (int f = 0; f < 4; f++)
        #pragma unroll
        for (int g = 0; g < 2; g++)
            #pragma unroll
            for (int i = 0; i < 4; i++) acc[f][g][i] = 0.0f;

    // prologue gather
    float4 fa[4];
    {
        int idx = sIdx[m * CHUNKS + 0];
        if (idx >= 0) {
            const float4* p = (const float4*)features + (size_t)idx * 16 + q * 4;
            #pragma unroll
            for (int i = 0; i < 4; i++) fa[i] = p[i];
        } else {
            #pragma unroll
            for (int i = 0; i < 4; i++) fa[i] = make_float4(0.f, 0.f, 0.f, 0.f);
        }
    }

    // ---- mainloop ----
    for (int c = 0; c < CHUNKS; c++) {
        const int abuf = c & 1;

        // B fragments for this chunk: 8 x LDG.128 (issued early, L2-hit)
        uint4 Bh[4], Bl[4];
        {
            const uint4* bh = g_BfragHi + ((size_t)(c * 4) * 8 + wn) * 32 + l;
            const uint4* bl = g_BfragLo + ((size_t)(c * 4) * 8 + wn) * 32 + l;
            #pragma unroll
            for (int ks = 0; ks < 4; ks++) {
                Bh[ks] = bh[ks * 8 * 32];
                Bl[ks] = bl[ks * 8 * 32];
            }
        }

        // convert fa -> bf16 hi/lo, STS into A[abuf]
        {
            uint32_t hi[8], lo[8];
            const float* ff = (const float*)fa;
            #pragma unroll
            for (int i = 0; i < 8; i++) {
                hi[i] = pack_hi(ff[2 * i], ff[2 * i + 1]);
                lo[i] = pack_lo(ff[2 * i], ff[2 * i + 1]);
            }
            uint32_t aB = sAb + abuf * A_BUF + m * A_ROW + q * 32;
            sts128(aB,      hi);
            sts128(aB + 16, hi + 4);
            sts128(aB + A_HALF,      lo);
            sts128(aB + A_HALF + 16, lo + 4);
        }

        // gather next chunk's A (hidden under compute)
        if (c + 1 < CHUNKS) {
            int idx = sIdx[m * CHUNKS + c + 1];
            if (idx >= 0) {
                const float4* p = (const float4*)features + (size_t)idx * 16 + q * 4;
                #pragma unroll
                for (int i = 0; i < 4; i++) fa[i] = p[i];
            } else {
                #pragma unroll
                for (int i = 0; i < 4; i++) fa[i] = make_float4(0.f, 0.f, 0.f, 0.f);
            }
        }

        __syncthreads();

        const uint32_t aHiB = sAb + abuf * A_BUF + aOffBase;
        #pragma unroll
        for (int ks = 0; ks < 4; ks++) {
            uint32_t ah[4][4], al[4][4];
            #pragma unroll
            for (int f = 0; f < 4; f++) {
                ldsm4(ah[f], aHiB + f * 16 * A_ROW + ks * 32);
                ldsm4(al[f], aHiB + A_HALF + f * 16 * A_ROW + ks * 32);
            }
            const uint32_t* bh = (const uint32_t*)&Bh[ks];
            const uint32_t* bl = (const uint32_t*)&Bl[ks];
            #pragma unroll
            for (int f = 0; f < 4; f++) {
                #pragma unroll
                for (int g = 0; g < 2; g++) {
                    mma16816(acc[f][g], ah[f], bh + g * 2);   // hi*hi
                    mma16816(acc[f][g], ah[f], bl + g * 2);   // hi*lo
                    mma16816(acc[f][g], al[f], bh + g * 2);   // lo*hi
                }
            }
        }
        // one sync per iter is hazard-safe with double-buffered A
    }

    // ---- epilogue: LayerNorm + ReLU ----
    #pragma unroll
    for (int f = 0; f < 4; f++) {
        #pragma unroll
        for (int h = 0; h < 2; h++) {
            float s = 0.f, sq = 0.f;
            #pragma unroll
            for (int g = 0; g < 2; g++) {
                float v0 = acc[f][g][h * 2], v1 = acc[f][g][h * 2 + 1];
                s += v0 + v1;
                sq += v0 * v0 + v1 * v1;
            }
            s  += __shfl_xor_sync(0xffffffffu, s, 1);
            sq += __shfl_xor_sync(0xffffffffu, sq, 1);
            s  += __shfl_xor_sync(0xffffffffu, s, 2);
            sq += __shfl_xor_sync(0xffffffffu, sq, 2);
            if ((l & 3) == 0) {
                int R = f * 16 + h * 8 + (l >> 2);
                sRed[R * 8 + wn] = make_float2(s, sq);
            }
        }
    }
    __syncthreads();

    const float invC = 1.0f / (float)COUT;
    #pragma unroll
    for (int f = 0; f < 4; f++) {
        #pragma unroll
        for (int h = 0; h < 2; h++) {
            int R = f * 16 + h * 8 + (l >> 2);
            float st = 0.f, sqt = 0.f;
            #pragma unroll
            for (int w = 0; w < 8; w++) {
                float2 p = sRed[R * 8 + w];
                st += p.x; sqt += p.y;
            }
            float mu  = st * invC;
            float var = sqt * invC - mu * mu;
            float rs  = rsqrtf(var + 1e-3f);
            int valid = sVal[R];
            int grow  = r0 + R;
            if (grow < BK) {
                float* op = outF + (size_t)grow * COUT;
                #pragma unroll
                for (int g = 0; g < 2; g++) {
                    int C = wn * 16 + g * 8 + (l & 3) * 2;
                    float2 gm = *(const float2*)(gamma + C);
                    float2 bt = *(const float2*)(beta + C);
                    float v0 = acc[f][g][h * 2], v1 = acc[f][g][h * 2 + 1];
                    float2 o;
                    o.x = valid ? fmaxf((v0 - mu) * rs * gm.x + bt.x, 0.f) : 0.f;
                    o.y = valid ? fmaxf((v1 - mu) * rs * gm.y + bt.y, 0.f) : 0.f;
                    *(float2*)(op + C) = o;
                }
            }
        }
    }
}

// =============================================================================
extern "C" void kernel_launch(void* const* d_in, const int* in_sizes, int n_in,
                              void* d_out, int out_size)
{
    const float* features = (const float*)d_in[0];
    const float* center   = (const float*)d_in[1];
    const int*   voxel    = (const int*)d_in[2];     // int32 (JAX x64 disabled)
    const int*   num_list = (const int*)d_in[3];
    const float* W        = (const float*)d_in[4];
    const float* gamma    = (const float*)d_in[5];
    const float* beta     = (const float*)d_in[6];

    int B    = in_sizes[3];
    int Cout = in_sizes[5];
    int M    = in_sizes[1] / 3;
    int K3r  = in_sizes[2] / M;
    int Cin  = in_sizes[4] / (K3r * Cout);
    int N    = in_sizes[0] / Cin;
    int K    = out_size / (B * (Cout + 4));
    int BK   = B * K;

    float* out  = (float*)d_out;
    float* outC = out + (size_t)BK * Cout;

    prep_b_kernel<<<(BFRAG_N + 255) / 256, 256>>>(W);

    int grid = (BK + TM - 1) / TM;
    fused_mma_kernel<<<grid, NTHR>>>(
        features, center, voxel, num_list, gamma, beta, out, outC,
        N, M, B, K, BK);
}

// round 8
// speedup vs baseline: 2.3846x; 1.1104x over previous
#include <cuda_runtime.h>
#include <cuda_bf16.h>
#include <cstdint>

// ---------------- problem shape constants ----------------
#define CHUNKS 27      // K3 neighbors = 27 K-chunks of 64
#define CIN    64
#define COUT   128
#define TM     64      // rows per CTA
#define NTHR   256

// A smem: 2 buffers x [hi 64x144B | lo 64x144B]
#define A_ROW   144
#define A_HALF  (64 * A_ROW)        // 9216
#define A_BUF   (2 * A_HALF)        // 18432

// B fragment images: [27][4 ks][8 n16blk][32 lanes] x uint4 (16B), hi and lo
#define BFRAG_N (CHUNKS * 4 * 8 * 32)
__device__ __align__(16) uint4 g_BfragHi[BFRAG_N];
__device__ __align__(16) uint4 g_BfragLo[BFRAG_N];

// ---------------- asm helpers ----------------
__device__ __forceinline__ uint32_t smem_u32(const void* p) {
    return (uint32_t)__cvta_generic_to_shared(p);
}
__device__ __forceinline__ void sts128(uint32_t addr, const uint32_t* r) {
    asm volatile("st.shared.v4.b32 [%0], {%1,%2,%3,%4};"
                 :: "r"(addr), "r"(r[0]), "r"(r[1]), "r"(r[2]), "r"(r[3]) : "memory");
}
__device__ __forceinline__ void ldsm4(uint32_t* r, uint32_t addr) {
    asm volatile("ldmatrix.sync.aligned.m8n8.x4.shared.b16 {%0,%1,%2,%3}, [%4];"
                 : "=r"(r[0]), "=r"(r[1]), "=r"(r[2]), "=r"(r[3]) : "r"(addr));
}
__device__ __forceinline__ void mma16816(float* d, const uint32_t* a, const uint32_t* b) {
    asm volatile(
        "mma.sync.aligned.m16n8k16.row.col.f32.bf16.bf16.f32 "
        "{%0,%1,%2,%3}, {%4,%5,%6,%7}, {%8,%9}, {%0,%1,%2,%3};"
        : "+f"(d[0]), "+f"(d[1]), "+f"(d[2]), "+f"(d[3])
        : "r"(a[0]), "r"(a[1]), "r"(a[2]), "r"(a[3]), "r"(b[0]), "r"(b[1]));
}
__device__ __forceinline__ uint32_t pack_hi(float v0, float v1) {
    return __byte_perm(__float_as_uint(v0), __float_as_uint(v1), 0x7632);
}
__device__ __forceinline__ uint32_t pack_lo(float v0, float v1) {
    float h0 = __uint_as_float(__float_as_uint(v0) & 0xFFFF0000u);
    float h1 = __uint_as_float(__float_as_uint(v1) & 0xFFFF0000u);
    float l0 = v0 - h0, l1 = v1 - h1;
    uint32_t r;
    asm("cvt.rn.bf16x2.f32 %0, %1, %2;" : "=r"(r) : "f"(l1), "f"(l0));
    return r;
}

// =============================================================================
// Prep: W -> bf16 hi/lo images in exact mma B-fragment order.
// Entry e = ((c*4+ks)*8 + t)*32 + l  (layout unchanged from R7)
// =============================================================================
__global__ void prep_b_kernel(const float* __restrict__ W) {
    int e = blockIdx.x * blockDim.x + threadIdx.x;
    if (e >= BFRAG_N) return;
    int l  = e & 31;
    int t  = (e >> 5) & 7;
    int ks = (e >> 8) & 3;
    int c  = e >> 10;
    int r = l & 3, ncol = l >> 2;
    int n0 = t * 16 + ncol, n1 = n0 + 8;
    int kb = ks * 16 + 2 * r;
    const float* Wc = W + (size_t)c * CIN * COUT;
    float v0 = Wc[(size_t)(kb + 0) * COUT + n0];
    float v1 = Wc[(size_t)(kb + 1) * COUT + n0];
    float v2 = Wc[(size_t)(kb + 8) * COUT + n0];
    float v3 = Wc[(size_t)(kb + 9) * COUT + n0];
    float v4 = Wc[(size_t)(kb + 0) * COUT + n1];
    float v5 = Wc[(size_t)(kb + 1) * COUT + n1];
    float v6 = Wc[(size_t)(kb + 8) * COUT + n1];
    float v7 = Wc[(size_t)(kb + 9) * COUT + n1];
    uint4 hi, lo;
    hi.x = pack_hi(v0, v1); hi.y = pack_hi(v2, v3);
    hi.z = pack_hi(v4, v5); hi.w = pack_hi(v6, v7);
    lo.x = pack_lo(v0, v1); lo.y = pack_lo(v2, v3);
    lo.z = pack_lo(v4, v5); lo.w = pack_lo(v6, v7);
    g_BfragHi[e] = hi;
    g_BfragLo[e] = lo;
}

// =============================================================================
// Fused kernel: gather + bf16x3 mma GEMM + LN + ReLU + coords.
// Fully software-pipelined: B regs double-buffered one chunk ahead,
// A-STS for chunk c+1 issued behind mma of chunk c, gather two chunks ahead.
// =============================================================================
__global__ __launch_bounds__(NTHR)
void fused_mma_kernel(const float* __restrict__ features,
                      const float* __restrict__ center,
                      const int* __restrict__ voxel_idx,
                      const int* __restrict__ num_list,
                      const float* __restrict__ gamma,
                      const float* __restrict__ beta,
                      float* __restrict__ outF,
                      float* __restrict__ outC,
                      int N, int M, int B, int K, int BK)
{
    __shared__ __align__(16) unsigned char sA[A_BUF * 2];   // 36864
    __shared__ int    sIdx[TM * CHUNKS];
    __shared__ int    sSrc[TM];
    __shared__ int    sVal[TM];
    __shared__ float2 sRed[TM * 8];

    const uint32_t sAb = smem_u32(sA);
    const int tid = threadIdx.x;
    const int r0  = blockIdx.x * TM;

    // ---- bookkeeping + coords (tid < 64) ----
    if (tid < TM) {
        int g = r0 + tid;
        int valid = 0, srcRow = 0, b = 0;
        if (g < BK) {
            b = g / K;
            int j = g - b * K;
            int off = 0;
            for (int bb = 0; bb < b; bb++) off += num_list[bb];
            int nl = num_list[b];
            int end = nl < K ? nl : K;
            valid = (j < end) ? 1 : 0;
            long long s = (long long)off + j;
            if (s < 0) s = 0;
            if (s > (long long)(M - 1)) s = M - 1;
            srcRow = (int)s;
        }
        sVal[tid] = valid;
        sSrc[tid] = srcRow;
        if (g < BK) {
            float c0 = (b < B - 1) ? (float)(b + 1) : 0.0f;
            float x = 0.f, y = 0.f, z = 0.f;
            if (valid) {
                x = center[(size_t)srcRow * 3 + 0];
                y = center[(size_t)srcRow * 3 + 1];
                z = center[(size_t)srcRow * 3 + 2];
            }
            *(float4*)(outC + (size_t)g * 4) = make_float4(c0, x, y, z);
        }
    }
    __syncthreads();

    // ---- stage neighbor indices ----
    for (int e = tid; e < TM * CHUNKS; e += NTHR) {
        int m = e / CHUNKS, c = e - m * CHUNKS;
        int v = voxel_idx[(size_t)sSrc[m] * CHUNKS + c];
        sIdx[e] = (v < 0) ? -1 : (v > N - 1 ? N - 1 : v);
    }
    __syncthreads();

    // producer mapping
    const int m = tid >> 2, q = tid & 3;
    // consumer mapping: 1(M) x 8(N) warp grid, warp tile 64x16
    const int l  = tid & 31;
    const int wn = tid >> 5;
    const uint32_t aOffBase = (uint32_t)((l & 15) * A_ROW + ((l >> 4) << 4));
    const uint32_t bIdxBase = (uint32_t)(wn * 32 + l);

    float acc[4][2][4];
    #pragma unroll
    for (int f = 0; f < 4; f++)
        #pragma unroll
        for (int g = 0; g < 2; g++)
            #pragma unroll
            for (int i = 0; i < 4; i++) acc[f][g][i] = 0.0f;

    // gather helper
    auto gatherA = [&](int c, float4* fa) {
        int idx = sIdx[m * CHUNKS + c];
        if (idx >= 0) {
            const float4* p = (const float4*)features + (size_t)idx * 16 + q * 4;
            #pragma unroll
            for (int i = 0; i < 4; i++) fa[i] = p[i];
        } else {
            #pragma unroll
            for (int i = 0; i < 4; i++) fa[i] = make_float4(0.f, 0.f, 0.f, 0.f);
        }
    };
    auto loadB = [&](int c, uint4 (&Bh)[4], uint4 (&Bl)[4]) {
        const uint4* bh = g_BfragHi + ((size_t)(c * 4) * 8) * 32 + bIdxBase;
        const uint4* bl = g_BfragLo + ((size_t)(c * 4) * 8) * 32 + bIdxBase;
        #pragma unroll
        for (int ks = 0; ks < 4; ks++) {
            Bh[ks] = bh[ks * 8 * 32];
            Bl[ks] = bl[ks * 8 * 32];
        }
    };
    auto convertStoreA = [&](const float4* fa, int abuf) {
        uint32_t hi[8], lo[8];
        const float* ff = (const float*)fa;
        #pragma unroll
        for (int i = 0; i < 8; i++) {
            hi[i] = pack_hi(ff[2 * i], ff[2 * i + 1]);
            lo[i] = pack_lo(ff[2 * i], ff[2 * i + 1]);
        }
        uint32_t aB = sAb + abuf * A_BUF + m * A_ROW + q * 32;
        sts128(aB,      hi);
        sts128(aB + 16, hi + 4);
        sts128(aB + A_HALF,      lo);
        sts128(aB + A_HALF + 16, lo + 4);
    };

    uint4 B0h[4], B0l[4], B1h[4], B1l[4];
    float4 fa[4];

    // ---- prologue: B(0), A(0) staged, fa holds A(1) ----
    loadB(0, B0h, B0l);
    gatherA(0, fa);
    convertStoreA(fa, 0);
    gatherA(1, fa);
    __syncthreads();

    // one pipelined step: mma chunk c with (BhC,BlC); prefetch B(c+1) into
    // (BhN,BlN); STS A(c+1) (from fa) into buf (c+1)&1; gather A(c+2).
    auto step = [&](int c, uint4 (&BhC)[4], uint4 (&BlC)[4],
                    uint4 (&BhN)[4], uint4 (&BlN)[4]) {
        if (c + 1 < CHUNKS) loadB(c + 1, BhN, BlN);   // LDG early, used next iter

        const uint32_t aHiB = sAb + (c & 1) * A_BUF + aOffBase;
        #pragma unroll
        for (int ks = 0; ks < 4; ks++) {
            uint32_t ah[4][4], al[4][4];
            #pragma unroll
            for (int f = 0; f < 4; f++) {
                ldsm4(ah[f], aHiB + f * 16 * A_ROW + ks * 32);
                ldsm4(al[f], aHiB + A_HALF + f * 16 * A_ROW + ks * 32);
            }
            const uint32_t* bh = (const uint32_t*)&BhC[ks];
            const uint32_t* bl = (const uint32_t*)&BlC[ks];
            #pragma unroll
            for (int f = 0; f < 4; f++) {
                #pragma unroll
                for (int g = 0; g < 2; g++) {
                    mma16816(acc[f][g], ah[f], bh + g * 2);   // hi*hi
                    mma16816(acc[f][g], ah[f], bl + g * 2);   // hi*lo
                    mma16816(acc[f][g], al[f], bh + g * 2);   // lo*hi
                }
            }
        }

        if (c + 1 < CHUNKS) {
            convertStoreA(fa, (c + 1) & 1);           // overlaps mma above
            if (c + 2 < CHUNKS) gatherA(c + 2, fa);   // two chunks ahead
        }
        __syncthreads();
    };

    // 13 pairs (chunks 0..25) + tail chunk 26 (even -> B0)
    #pragma unroll 1
    for (int c = 0; c < CHUNKS - 1; c += 2) {
        step(c,     B0h, B0l, B1h, B1l);
        step(c + 1, B1h, B1l, B0h, B0l);
    }
    step(CHUNKS - 1, B0h, B0l, B1h, B1l);

    // ---- epilogue: LayerNorm + ReLU ----
    #pragma unroll
    for (int f = 0; f < 4; f++) {
        #pragma unroll
        for (int h = 0; h < 2; h++) {
            float s = 0.f, sq = 0.f;
            #pragma unroll
            for (int g = 0; g < 2; g++) {
                float v0 = acc[f][g][h * 2], v1 = acc[f][g][h * 2 + 1];
                s += v0 + v1;
                sq += v0 * v0 + v1 * v1;
            }
            s  += __shfl_xor_sync(0xffffffffu, s, 1);
            sq += __shfl_xor_sync(0xffffffffu, sq, 1);
            s  += __shfl_xor_sync(0xffffffffu, s, 2);
            sq += __shfl_xor_sync(0xffffffffu, sq, 2);
            if ((l & 3) == 0) {
                int R = f * 16 + h * 8 + (l >> 2);
                sRed[R * 8 + wn] = make_float2(s, sq);
            }
        }
    }
    __syncthreads();

    const float invC = 1.0f / (float)COUT;
    #pragma unroll
    for (int f = 0; f < 4; f++) {
        #pragma unroll
        for (int h = 0; h < 2; h++) {
            int R = f * 16 + h * 8 + (l >> 2);
            float st = 0.f, sqt = 0.f;
            #pragma unroll
            for (int w = 0; w < 8; w++) {
                float2 p = sRed[R * 8 + w];
                st += p.x; sqt += p.y;
            }
            float mu  = st * invC;
            float var = sqt * invC - mu * mu;
            float rs  = rsqrtf(var + 1e-3f);
            int valid = sVal[R];
            int grow  = r0 + R;
            if (grow < BK) {
                float* op = outF + (size_t)grow * COUT;
                #pragma unroll
                for (int g = 0; g < 2; g++) {
                    int C = wn * 16 + g * 8 + (l & 3) * 2;
                    float2 gm = *(const float2*)(gamma + C);
                    float2 bt = *(const float2*)(beta + C);
                    float v0 = acc[f][g][h * 2], v1 = acc[f][g][h * 2 + 1];
                    float2 o;
                    o.x = valid ? fmaxf((v0 - mu) * rs * gm.x + bt.x, 0.f) : 0.f;
                    o.y = valid ? fmaxf((v1 - mu) * rs * gm.y + bt.y, 0.f) : 0.f;
                    *(float2*)(op + C) = o;
                }
            }
        }
    }
}

// =============================================================================
extern "C" void kernel_launch(void* const* d_in, const int* in_sizes, int n_in,
                              void* d_out, int out_size)
{
    const float* features = (const float*)d_in[0];
    const float* center   = (const float*)d_in[1];
    const int*   voxel    = (const int*)d_in[2];     // int32 (JAX x64 disabled)
    const int*   num_list = (const int*)d_in[3];
    const float* W        = (const float*)d_in[4];
    const float* gamma    = (const float*)d_in[5];
    const float* beta     = (const float*)d_in[6];

    int B    = in_sizes[3];
    int Cout = in_sizes[5];
    int M    = in_sizes[1] / 3;
    int K3r  = in_sizes[2] / M;
    int Cin  = in_sizes[4] / (K3r * Cout);
    int N    = in_sizes[0] / Cin;
    int K    = out_size / (B * (Cout + 4));
    int BK   = B * K;

    float* out  = (float*)d_out;
    float* outC = out + (size_t)BK * Cout;

    prep_b_kernel<<<(BFRAG_N + 255) / 256, 256>>>(W);

    int grid = (BK + TM - 1) / TM;
    fused_mma_kernel<<<grid, NTHR>>>(
        features, center, voxel, num_list, gamma, beta, out, outC,
        N, M, B, K, BK);
}

// round 9
// speedup vs baseline: 2.4903x; 1.0444x over previous
#include <cuda_runtime.h>
#include <cuda_bf16.h>
#include <cstdint>

// ---------------- problem shape constants ----------------
#define CHUNKS 27      // K3 neighbors = 27 K-chunks of 64
#define CIN    64
#define COUT   128
#define TM     64      // rows per CTA
#define NTHR   512     // 16 warps: 8 n16-blocks x 2 k-halves

// A smem: 2 buffers x [hi 64x144B | lo 64x144B]
#define A_ROW   144
#define A_HALF  (64 * A_ROW)        // 9216
#define A_BUF   (2 * A_HALF)        // 18432

// partial-acc exchange overlay (on sA): [wn][row 0..63][col 0..16] stride 17
#define ACC_STRIDE 17
#define ACC_WN     (64 * ACC_STRIDE)   // 1088 floats per wn

// B fragment images: [27][4 ks][8 n16blk][32 lanes] x uint4, hi and lo
#define BFRAG_N (CHUNKS * 4 * 8 * 32)
__device__ __align__(16) uint4 g_BfragHi[BFRAG_N];
__device__ __align__(16) uint4 g_BfragLo[BFRAG_N];

// ---------------- asm helpers ----------------
__device__ __forceinline__ uint32_t smem_u32(const void* p) {
    return (uint32_t)__cvta_generic_to_shared(p);
}
__device__ __forceinline__ void sts128(uint32_t addr, const uint32_t* r) {
    asm volatile("st.shared.v4.b32 [%0], {%1,%2,%3,%4};"
                 :: "r"(addr), "r"(r[0]), "r"(r[1]), "r"(r[2]), "r"(r[3]) : "memory");
}
__device__ __forceinline__ void ldsm4(uint32_t* r, uint32_t addr) {
    asm volatile("ldmatrix.sync.aligned.m8n8.x4.shared.b16 {%0,%1,%2,%3}, [%4];"
                 : "=r"(r[0]), "=r"(r[1]), "=r"(r[2]), "=r"(r[3]) : "r"(addr));
}
__device__ __forceinline__ void mma16816(float* d, const uint32_t* a, const uint32_t* b) {
    asm volatile(
        "mma.sync.aligned.m16n8k16.row.col.f32.bf16.bf16.f32 "
        "{%0,%1,%2,%3}, {%4,%5,%6,%7}, {%8,%9}, {%0,%1,%2,%3};"
        : "+f"(d[0]), "+f"(d[1]), "+f"(d[2]), "+f"(d[3])
        : "r"(a[0]), "r"(a[1]), "r"(a[2]), "r"(a[3]), "r"(b[0]), "r"(b[1]));
}
__device__ __forceinline__ uint32_t pack_hi(float v0, float v1) {
    return __byte_perm(__float_as_uint(v0), __float_as_uint(v1), 0x7632);
}
__device__ __forceinline__ uint32_t pack_lo(float v0, float v1) {
    float h0 = __uint_as_float(__float_as_uint(v0) & 0xFFFF0000u);
    float h1 = __uint_as_float(__float_as_uint(v1) & 0xFFFF0000u);
    float l0 = v0 - h0, l1 = v1 - h1;
    uint32_t r;
    asm("cvt.rn.bf16x2.f32 %0, %1, %2;" : "=r"(r) : "f"(l1), "f"(l0));
    return r;
}

// =============================================================================
// Prep: W -> bf16 hi/lo images in exact mma B-fragment order (R7 layout).
// =============================================================================
__global__ void prep_b_kernel(const float* __restrict__ W) {
    int e = blockIdx.x * blockDim.x + threadIdx.x;
    if (e >= BFRAG_N) return;
    int l  = e & 31;
    int t  = (e >> 5) & 7;
    int ks = (e >> 8) & 3;
    int c  = e >> 10;
    int r = l & 3, ncol = l >> 2;
    int n0 = t * 16 + ncol, n1 = n0 + 8;
    int kb = ks * 16 + 2 * r;
    const float* Wc = W + (size_t)c * CIN * COUT;
    float v0 = Wc[(size_t)(kb + 0) * COUT + n0];
    float v1 = Wc[(size_t)(kb + 1) * COUT + n0];
    float v2 = Wc[(size_t)(kb + 8) * COUT + n0];
    float v3 = Wc[(size_t)(kb + 9) * COUT + n0];
    float v4 = Wc[(size_t)(kb + 0) * COUT + n1];
    float v5 = Wc[(size_t)(kb + 1) * COUT + n1];
    float v6 = Wc[(size_t)(kb + 8) * COUT + n1];
    float v7 = Wc[(size_t)(kb + 9) * COUT + n1];
    uint4 hi, lo;
    hi.x = pack_hi(v0, v1); hi.y = pack_hi(v2, v3);
    hi.z = pack_hi(v4, v5); hi.w = pack_hi(v6, v7);
    lo.x = pack_lo(v0, v1); lo.y = pack_lo(v2, v3);
    lo.z = pack_lo(v4, v5); lo.w = pack_lo(v6, v7);
    g_BfragHi[e] = hi;
    g_BfragLo[e] = lo;
}

// =============================================================================
// Fused kernel. 16 warps: wn = warp>>1 (n16 block), wk = warp&1 (k half).
// Each warp accumulates its k-half; partials merged in smem before LN.
// =============================================================================
__global__ __launch_bounds__(NTHR)
void fused_mma_kernel(const float* __restrict__ features,
                      const float* __restrict__ center,
                      const int* __restrict__ voxel_idx,
                      const int* __restrict__ num_list,
                      const float* __restrict__ gamma,
                      const float* __restrict__ beta,
                      float* __restrict__ outF,
                      float* __restrict__ outC,
                      int N, int M, int B, int K, int BK)
{
    __shared__ __align__(16) unsigned char sA[A_BUF * 2];   // 36864 (overlaid by sAcc later)
    __shared__ int    sIdx[TM * CHUNKS];
    __shared__ int    sSrc[TM];
    __shared__ int    sVal[TM];
    __shared__ float2 sRed[TM * 8];

    const uint32_t sAb = smem_u32(sA);
    const int tid = threadIdx.x;
    const int r0  = blockIdx.x * TM;

    // ---- bookkeeping + coords (tid < 64) ----
    if (tid < TM) {
        int g = r0 + tid;
        int valid = 0, srcRow = 0, b = 0;
        if (g < BK) {
            b = g / K;
            int j = g - b * K;
            int off = 0;
            for (int bb = 0; bb < b; bb++) off += num_list[bb];
            int nl = num_list[b];
            int end = nl < K ? nl : K;
            valid = (j < end) ? 1 : 0;
            long long s = (long long)off + j;
            if (s < 0) s = 0;
            if (s > (long long)(M - 1)) s = M - 1;
            srcRow = (int)s;
        }
        sVal[tid] = valid;
        sSrc[tid] = srcRow;
        if (g < BK) {
            float c0 = (b < B - 1) ? (float)(b + 1) : 0.0f;
            float x = 0.f, y = 0.f, z = 0.f;
            if (valid) {
                x = center[(size_t)srcRow * 3 + 0];
                y = center[(size_t)srcRow * 3 + 1];
                z = center[(size_t)srcRow * 3 + 2];
            }
            *(float4*)(outC + (size_t)g * 4) = make_float4(c0, x, y, z);
        }
    }
    __syncthreads();

    // ---- stage neighbor indices ----
    for (int e = tid; e < TM * CHUNKS; e += NTHR) {
        int m = e / CHUNKS, c = e - m * CHUNKS;
        int v = voxel_idx[(size_t)sSrc[m] * CHUNKS + c];
        sIdx[e] = (v < 0) ? -1 : (v > N - 1 ? N - 1 : v);
    }
    __syncthreads();

    // producer mapping: 512 threads, each owns row m, 8 channels (q*8..q*8+7)
    const int m = tid >> 3, q = tid & 7;
    // consumer mapping
    const int l   = tid & 31;
    const int wid = tid >> 5;        // 0..15
    const int wk  = wid & 1;         // k half
    const int wn  = wid >> 1;        // n16 block 0..7
    const uint32_t aOffBase = (uint32_t)((l & 15) * A_ROW + ((l >> 4) << 4));
    const uint32_t bIdxBase = (uint32_t)(wn * 32 + l);

    float acc[4][2][4];
    #pragma unroll
    for (int f = 0; f < 4; f++)
        #pragma unroll
        for (int g = 0; g < 2; g++)
            #pragma unroll
            for (int i = 0; i < 4; i++) acc[f][g][i] = 0.0f;

    auto gatherA = [&](int c, float4* fa) {
        int idx = sIdx[m * CHUNKS + c];
        if (idx >= 0) {
            const float4* p = (const float4*)features + (size_t)idx * 16 + q * 2;
            fa[0] = p[0];
            fa[1] = p[1];
        } else {
            fa[0] = make_float4(0.f, 0.f, 0.f, 0.f);
            fa[1] = make_float4(0.f, 0.f, 0.f, 0.f);
        }
    };
    // this warp's two k-steps: ks = 2*wk, 2*wk+1
    auto loadB = [&](int c, uint4 (&Bh)[2], uint4 (&Bl)[2]) {
        const uint4* bh = g_BfragHi + ((size_t)(c * 4 + 2 * wk) * 8) * 32 + bIdxBase;
        const uint4* bl = g_BfragLo + ((size_t)(c * 4 + 2 * wk) * 8) * 32 + bIdxBase;
        Bh[0] = bh[0];       Bl[0] = bl[0];
        Bh[1] = bh[8 * 32];  Bl[1] = bl[8 * 32];
    };
    auto convertStoreA = [&](const float4* fa, int abuf) {
        uint32_t hi[4], lo[4];
        const float* ff = (const float*)fa;
        #pragma unroll
        for (int i = 0; i < 4; i++) {
            hi[i] = pack_hi(ff[2 * i], ff[2 * i + 1]);
            lo[i] = pack_lo(ff[2 * i], ff[2 * i + 1]);
        }
        uint32_t aB = sAb + abuf * A_BUF + m * A_ROW + q * 16;
        sts128(aB,          hi);
        sts128(aB + A_HALF, lo);
    };

    uint4 B0h[2], B0l[2], B1h[2], B1l[2];
    float4 fa[2];

    // ---- prologue ----
    loadB(0, B0h, B0l);
    gatherA(0, fa);
    convertStoreA(fa, 0);
    gatherA(1, fa);
    __syncthreads();

    auto step = [&](int c, uint4 (&BhC)[2], uint4 (&BlC)[2],
                    uint4 (&BhN)[2], uint4 (&BlN)[2]) {
        if (c + 1 < CHUNKS) loadB(c + 1, BhN, BlN);

        const uint32_t aBase = sAb + (c & 1) * A_BUF + aOffBase;
        #pragma unroll
        for (int ks2 = 0; ks2 < 2; ks2++) {
            const int ks = 2 * wk + ks2;
            uint32_t ah[4][4], al[4][4];
            #pragma unroll
            for (int f = 0; f < 4; f++) {
                ldsm4(ah[f], aBase + f * 16 * A_ROW + ks * 32);
                ldsm4(al[f], aBase + A_HALF + f * 16 * A_ROW + ks * 32);
            }
            const uint32_t* bh = (const uint32_t*)&BhC[ks2];
            const uint32_t* bl = (const uint32_t*)&BlC[ks2];
            #pragma unroll
            for (int f = 0; f < 4; f++) {
                #pragma unroll
                for (int g = 0; g < 2; g++) {
                    mma16816(acc[f][g], ah[f], bh + g * 2);   // hi*hi
                    mma16816(acc[f][g], ah[f], bl + g * 2);   // hi*lo
                    mma16816(acc[f][g], al[f], bh + g * 2);   // lo*hi
                }
            }
        }

        if (c + 1 < CHUNKS) {
            convertStoreA(fa, (c + 1) & 1);
            if (c + 2 < CHUNKS) gatherA(c + 2, fa);
        }
        __syncthreads();
    };

    #pragma unroll 1
    for (int c = 0; c < CHUNKS - 1; c += 2) {
        step(c,     B0h, B0l, B1h, B1l);
        step(c + 1, B1h, B1l, B0h, B0l);
    }
    step(CHUNKS - 1, B0h, B0l, B1h, B1l);

    // ---- merge k-half partials (sAcc overlays sA; mainloop done) ----
    float* sAcc = (float*)sA;
    if (wk == 1) {
        #pragma unroll
        for (int f = 0; f < 4; f++)
            #pragma unroll
            for (int g = 0; g < 2; g++)
                #pragma unroll
                for (int i = 0; i < 4; i++) {
                    int R  = f * 16 + (i >> 1) * 8 + (l >> 2);
                    int cc = g * 8 + (l & 3) * 2 + (i & 1);
                    sAcc[wn * ACC_WN + R * ACC_STRIDE + cc] = acc[f][g][i];
                }
    }
    __syncthreads();
    if (wk == 0) {
        #pragma unroll
        for (int f = 0; f < 4; f++)
            #pragma unroll
            for (int g = 0; g < 2; g++)
                #pragma unroll
                for (int i = 0; i < 4; i++) {
                    int R  = f * 16 + (i >> 1) * 8 + (l >> 2);
                    int cc = g * 8 + (l & 3) * 2 + (i & 1);
                    acc[f][g][i] += sAcc[wn * ACC_WN + R * ACC_STRIDE + cc];
                }
        // LN partial stats
        #pragma unroll
        for (int f = 0; f < 4; f++) {
            #pragma unroll
            for (int h = 0; h < 2; h++) {
                float s = 0.f, sq = 0.f;
                #pragma unroll
                for (int g = 0; g < 2; g++) {
                    float v0 = acc[f][g][h * 2], v1 = acc[f][g][h * 2 + 1];
                    s += v0 + v1;
                    sq += v0 * v0 + v1 * v1;
                }
                s  += __shfl_xor_sync(0xffffffffu, s, 1);
                sq += __shfl_xor_sync(0xffffffffu, sq, 1);
                s  += __shfl_xor_sync(0xffffffffu, s, 2);
                sq += __shfl_xor_sync(0xffffffffu, sq, 2);
                if ((l & 3) == 0) {
                    int R = f * 16 + h * 8 + (l >> 2);
                    sRed[R * 8 + wn] = make_float2(s, sq);
                }
            }
        }
    }
    __syncthreads();

    if (wk == 0) {
        const float invC = 1.0f / (float)COUT;
        #pragma unroll
        for (int f = 0; f < 4; f++) {
            #pragma unroll
            for (int h = 0; h < 2; h++) {
                int R = f * 16 + h * 8 + (l >> 2);
                float st = 0.f, sqt = 0.f;
                #pragma unroll
                for (int w = 0; w < 8; w++) {
                    float2 p = sRed[R * 8 + w];
                    st += p.x; sqt += p.y;
                }
                float mu  = st * invC;
                float var = sqt * invC - mu * mu;
                float rs  = rsqrtf(var + 1e-3f);
                int valid = sVal[R];
                int grow  = r0 + R;
                if (grow < BK) {
                    float* op = outF + (size_t)grow * COUT;
                    #pragma unroll
                    for (int g = 0; g < 2; g++) {
                        int C = wn * 16 + g * 8 + (l & 3) * 2;
                        float2 gm = *(const float2*)(gamma + C);
                        float2 bt = *(const float2*)(beta + C);
                        float v0 = acc[f][g][h * 2], v1 = acc[f][g][h * 2 + 1];
                        float2 o;
                        o.x = valid ? fmaxf((v0 - mu) * rs * gm.x + bt.x, 0.f) : 0.f;
                        o.y = valid ? fmaxf((v1 - mu) * rs * gm.y + bt.y, 0.f) : 0.f;
                        *(float2*)(op + C) = o;
                    }
                }
            }
        }
    }
}

// =============================================================================
extern "C" void kernel_launch(void* const* d_in, const int* in_sizes, int n_in,
                              void* d_out, int out_size)
{
    const float* features = (const float*)d_in[0];
    const float* center   = (const float*)d_in[1];
    const int*   voxel    = (const int*)d_in[2];     // int32 (JAX x64 disabled)
    const int*   num_list = (const int*)d_in[3];
    const float* W        = (const float*)d_in[4];
    const float* gamma    = (const float*)d_in[5];
    const float* beta     = (const float*)d_in[6];

    int B    = in_sizes[3];
    int Cout = in_sizes[5];
    int M    = in_sizes[1] / 3;
    int K3r  = in_sizes[2] / M;
    int Cin  = in_sizes[4] / (K3r * Cout);
    int N    = in_sizes[0] / Cin;
    int K    = out_size / (B * (Cout + 4));
    int BK   = B * K;

    float* out  = (float*)d_out;
    float* outC = out + (size_t)BK * Cout;

    prep_b_kernel<<<(BFRAG_N + 255) / 256, 256>>>(W);

    int grid = (BK + TM - 1) / TM;
    fused_mma_kernel<<<grid, NTHR>>>(
        features, center, voxel, num_list, gamma, beta, out, outC,
        N, M, B, K, BK);
}